// round 13
// baseline (speedup 1.0000x reference)
#include <cuda_runtime.h>
#include <cuda_fp16.h>

// ---------------- problem constants ----------------
#define MM    128
#define FF    1025
#define FPc   1088
#define TT    1024
#define NITER 20
#define LRc   0.3f
#define MOMc  0.9f
#define INVc  (2.0f / 4096.0f)

#define ROWS  32
#define NTHR  512
#define NCTA  128            // single wave, 32 rows/CTA, batch-pure
#define NJ    17             // 17 * 64 f = 1088
#define NC4M  12             // fp32 float4 CSR chunks per mel (48 slots >= max width ~46)

// ---------------- persistent tables ----------------
__device__ __half2 g_w01h[FPc];        // (w0,w1) fp16 — spec-update path
__device__ float2  g_w01f[FPc];        // (w0,w1) fp32 — clamp corrections
__device__ unsigned char g_i0[FPc];    // clamped first mel index (<=126)
__device__ float4  g_csr4[NC4M*MM];    // fp32 CSR, chunk-major (y0 gather)
__device__ int     g_lonc[MM];         // lo | nc<<16
__device__ float4  g_G4[MM];           // tridiag (Gl, Gd, Gu, 0) = fb32^T * W16

// ---------------- prep1: per-f tables + per-mel fp32 CSR ----------------
__global__ void prep1_kernel(const float* __restrict__ fb) {
    const int blk = blockIdx.x;
    if (blk < 272) {
        const int warp = threadIdx.x >> 5;
        const int lane = threadIdx.x & 31;
        const int f = blk * 4 + warp;
        if (f >= FF) {
            if (f < FPc && lane == 0) {
                g_w01h[f] = __floats2half2_rn(0.f, 0.f);
                g_w01f[f] = make_float2(0.f, 0.f);
                g_i0[f] = 0;
            }
            return;
        }
        const float* fr = fb + f * MM;
        unsigned b0 = __ballot_sync(0xffffffffu, fr[lane]      > 0.f);
        unsigned b1 = __ballot_sync(0xffffffffu, fr[lane + 32] > 0.f);
        unsigned b2 = __ballot_sync(0xffffffffu, fr[lane + 64] > 0.f);
        unsigned b3 = __ballot_sync(0xffffffffu, fr[lane + 96] > 0.f);
        if (lane == 0) {
            int fm = b0 ? (__ffs(b0) - 1)
                   : b1 ? (32 + __ffs(b1) - 1)
                   : b2 ? (64 + __ffs(b2) - 1)
                   : b3 ? (96 + __ffs(b3) - 1) : -1;
            if (fm < 0) {
                g_w01h[f] = __floats2half2_rn(0.f, 0.f);
                g_w01f[f] = make_float2(0.f, 0.f);
                g_i0[f] = 0;
            } else {
                int i0 = fm > 126 ? 126 : fm;
                g_w01h[f] = __floats2half2_rn(fr[i0], fr[i0 + 1]);
                g_w01f[f] = make_float2(fr[i0], fr[i0 + 1]);
                g_i0[f]   = (unsigned char)i0;
            }
        }
    } else {
        __shared__ int s_mn[128], s_mx[128];
        const int m = blk - 272;
        const int t = threadIdx.x;
        int mn = FF, mx = -1;
        for (int f = t; f < FF; f += 128) {
            if (fb[f * MM + m] > 0.f) { mn = min(mn, f); mx = max(mx, f); }
        }
        s_mn[t] = mn; s_mx[t] = mx;
        __syncthreads();
        for (int s = 64; s > 0; s >>= 1) {
            if (t < s) { s_mn[t] = min(s_mn[t], s_mn[t + s]); s_mx[t] = max(s_mx[t], s_mx[t + s]); }
            __syncthreads();
        }
        const int lo_al = (s_mx[0] < 0) ? 0 : (s_mn[0] & ~3);
        int cnt = (s_mx[0] < 0) ? 0 : (s_mx[0] + 1 - lo_al);
        int cnt_al = (cnt + 3) & ~3;
        if (cnt_al > 4 * NC4M) cnt_al = 4 * NC4M;
        if (t == 0) g_lonc[m] = lo_al | ((cnt_al >> 2) << 16);
        if (t < 4 * NC4M) {
            float w = (lo_al + t < FF) ? fb[(lo_al + t) * MM + m] : 0.f;
            reinterpret_cast<float*>(g_csr4)[((t >> 2) * MM + m) * 4 + (t & 3)] = w;
        }
    }
}

// ---------------- prep2: tridiagonal G~ = fb32^T W16 (after prep1) ----------------
__global__ void prep2_kernel(const float* __restrict__ fb) {
    __shared__ float sl[128], sd[128], su[128];
    const int m = blockIdx.x;
    const int t = threadIdx.x;
    float l = 0.f, d = 0.f, u = 0.f;
    for (int f = t; f < FF; f += 128) {
        const float fbv = fb[f * MM + m];
        if (fbv > 0.f) {
            const float2 w = __half22float2(g_w01h[f]);
            const int i0 = (int)g_i0[f];
            if (i0 == m)          { d = fmaf(fbv, w.x, d); u = fmaf(fbv, w.y, u); }
            else if (i0 == m - 1) { l = fmaf(fbv, w.x, l); d = fmaf(fbv, w.y, d); }
        }
    }
    sl[t] = l; sd[t] = d; su[t] = u;
    __syncthreads();
    for (int s = 64; s > 0; s >>= 1) {
        if (t < s) { sl[t] += sl[t + s]; sd[t] += sd[t + s]; su[t] += su[t + s]; }
        __syncthreads();
    }
    if (t == 0) g_G4[m] = make_float4(sl[0], sd[0], su[0], 0.f);
}

// ---------------- SMEM layout (float offsets) ----------------
#define BCSTR    264                                  // bufc2 row stride (floats); pad pair at [0,1]
#define OFF_BC   0                                    // 32*264 = 8448
#define OFF_Y    (OFF_BC  + ROWS * BCSTR)             // 8448 ; 32*132
#define OFF_CORR (OFF_Y   + ROWS * 132)               // 12672 ; 32*132
#define OFF_W01H (OFF_CORR+ ROWS * 132)               // 16896 ; 1088
#define OFF_W01F (OFF_W01H+ FPc)                      // 17984 ; 2176 (float2)
#define OFF_I0   (OFF_W01F+ 2 * FPc)                  // 20160 ; 272
#define OFF_G4   (OFF_I0  + FPc / 4)                  // 20432 ; 512 (float4)
#define OFF_LONC (OFF_G4  + 4 * MM)                   // 20944 ; 128
#define STSTR    584                                  // stage row stride
#define OFF_STG  (OFF_LONC + MM)                      // 21072 ; 32*584 = 18688
#define SM_FLOATS (OFF_STG + ROWS * STSTR)            // 39760 floats = 159040 B

// ---------------- main kernel ----------------
__global__ __launch_bounds__(NTHR, 1)
void invmel_kernel(const float* __restrict__ melspec,
                   const float* __restrict__ spec_init,
                   float* __restrict__ out) {
    extern __shared__ float smem[];
    float*  s_bc   = smem + OFF_BC;                       // bufc pairs, float view
    float2* s_bc2  = reinterpret_cast<float2*>(s_bc);     // pair(m) at r*132 + 1 + m
    float*  s_y    = smem + OFF_Y;
    float*  s_corr = smem + OFF_CORR;
    unsigned int* s_w01h = reinterpret_cast<unsigned int*>(smem + OFF_W01H);
    float2* s_w01f = reinterpret_cast<float2*>(smem + OFF_W01F);
    unsigned char* s_i0 = reinterpret_cast<unsigned char*>(smem + OFF_I0);
    float4* s_G4   = reinterpret_cast<float4*>(smem + OFF_G4);
    int*    s_lonc = reinterpret_cast<int*>(smem + OFF_LONC);
    float*  s_stg  = smem + OFF_STG;

    const int tid  = threadIdx.x;
    const int row0 = blockIdx.x * ROWS;         // multiple of 32 -> batch-pure CTA
    const int b    = row0 >> 10;
    const int t0   = row0 & 1023;

    // ---- tables ----
    for (int i = tid; i < FPc; i += NTHR) {
        s_w01h[i] = reinterpret_cast<const unsigned int*>(g_w01h)[i];
        s_w01f[i] = g_w01f[i];
        s_i0[i]   = g_i0[i];
    }
    if (tid < MM) { s_lonc[tid] = g_lonc[tid]; s_G4[tid] = g_G4[tid]; }
    // zero bufc pairs (incl. pads) and corr
    for (int i = tid; i < ROWS * BCSTR; i += NTHR) s_bc[i] = 0.f;
    for (int i = tid; i < ROWS * 132;   i += NTHR) s_corr[i] = 0.f;

    const int row = tid >> 4;        // 0..31
    const int q   = tid & 15;
    const int rb  = row * BCSTR;     // bufc float base
    const int yb  = row * 132;
    const int pb  = row * 132 + 1;   // pair base (float2 index)
    const size_t grow = (size_t)(row0 + row) * FF;

    // ---- spec master -> registers (68 f per lane) ----
    float4 spec[NJ];
    #pragma unroll
    for (int j = 0; j < NJ; ++j) {
        const int f = 64 * j + 4 * q;
        float4 v;
        v.x = (f + 0 < FF) ? spec_init[grow + f + 0] : 0.f;
        v.y = (f + 1 < FF) ? spec_init[grow + f + 1] : 0.f;
        v.z = (f + 2 < FF) ? spec_init[grow + f + 2] : 0.f;
        v.w = (f + 3 < FF) ? spec_init[grow + f + 3] : 0.f;
        spec[j] = v;
    }
    // ---- mel -> registers (8 mels per lane) ----
    float mel8[8];
    #pragma unroll
    for (int j = 0; j < 8; ++j) {
        const int m = 16 * j + q;
        mel8[j] = melspec[((size_t)b * MM + m) * TT + t0 + row];
    }
    __syncthreads();   // tables + zeros visible

    // ---- y0 = fb32 . spec_init (CSR gather from gmem) ; c = 0 ----
    float c8[8];
    #pragma unroll
    for (int j = 0; j < 8; ++j) {
        const int m  = 16 * j + q;
        const int lc = s_lonc[m];
        const int lo = lc & 0xffff;
        const int nc = lc >> 16;
        float a0 = 0.f, a1 = 0.f;
        for (int c = 0; c < nc; ++c) {
            const float4 w = g_csr4[c * MM + m];
            const int k = lo + 4 * c;
            const float sx = (k + 0 < FF) ? spec_init[grow + k + 0] : 0.f;
            const float sy = (k + 1 < FF) ? spec_init[grow + k + 1] : 0.f;
            const float sz = (k + 2 < FF) ? spec_init[grow + k + 2] : 0.f;
            const float sw = (k + 3 < FF) ? spec_init[grow + k + 3] : 0.f;
            a0 = fmaf(w.x, sx, a0);
            a1 = fmaf(w.y, sy, a1);
            a0 = fmaf(w.z, sz, a0);
            a1 = fmaf(w.w, sw, a1);
        }
        s_y[yb + m] = a0 + a1;
        c8[j] = 0.f;
    }
    __syncwarp();

    for (int it = 0; it < NITER; ++it) {
        // ==== phase A1: apply corr; diff; momentum state c; publish pairs ====
        #pragma unroll
        for (int j = 0; j < 8; ++j) {
            const int m = 16 * j + q;
            float yv = s_y[yb + m] + s_corr[yb + m];
            s_corr[yb + m] = 0.f;
            s_y[yb + m] = yv;                              // corrected y (= fb.spec_prev)
            const float d = mel8[j] - yv;
            c8[j] = fmaf(MOMc, c8[j], -INVc * d);
            float cn = __shfl_down_sync(0xffffffffu, c8[j], 1);
            if (j == 7 && q == 15) cn = 0.f;               // c[128] pad
            *reinterpret_cast<float2*>(s_bc + rb + 2 + 2 * m) = make_float2(c8[j], cn);
            if (j > 0 && q == 0)
                s_bc[rb + 2 + 2 * m - 1] = c8[j];          // fix prev group's q=15 .y slot
        }
        __syncwarp();

        // ==== phase A2: y <- y - LR * (G~ c)   (tridiagonal) ====
        #pragma unroll
        for (int j = 0; j < 8; ++j) {
            const int m = 16 * j + q;
            const float4 G = s_G4[m];
            const float cm1 = s_bc[rb + 2 * m];            // pair(m-1).x (m=0 -> pad 0)
            const float cp1 = s_bc[rb + 2 * m + 3];        // pair(m).y
            float acc = G.x * cm1;
            acc = fmaf(G.y, c8[j], acc);
            acc = fmaf(G.z, cp1, acc);
            s_y[yb + m] = fmaf(-LRc, acc, s_y[yb + m]);
        }

        // ==== phase C: buf_f = w16 . c pair; spec update + clamp corrections ====
        #pragma unroll
        for (int j = 0; j < NJ; ++j) {
            const int f = 64 * j + 4 * q;
            const uint4 wr = *reinterpret_cast<const uint4*>(s_w01h + f);
            const uchar4 ii = *reinterpret_cast<const uchar4*>(s_i0 + f);
            const float2 wA = __half22float2(*reinterpret_cast<const __half2*>(&wr.x));
            const float2 wB = __half22float2(*reinterpret_cast<const __half2*>(&wr.y));
            const float2 wC = __half22float2(*reinterpret_cast<const __half2*>(&wr.z));
            const float2 wD = __half22float2(*reinterpret_cast<const __half2*>(&wr.w));
            const float2 cA = s_bc2[pb + ii.x];
            const float2 cB = s_bc2[pb + ii.y];
            const float2 cC = s_bc2[pb + ii.z];
            const float2 cD = s_bc2[pb + ii.w];
            const float bf0 = fmaf(wA.x, cA.x, wA.y * cA.y);
            const float bf1 = fmaf(wB.x, cB.x, wB.y * cB.y);
            const float bf2 = fmaf(wC.x, cC.x, wC.y * cC.y);
            const float bf3 = fmaf(wD.x, cD.x, wD.y * cD.y);
            float4 sp = spec[j];
            const float n0 = fmaf(-LRc, bf0, sp.x);
            const float n1 = fmaf(-LRc, bf1, sp.y);
            const float n2 = fmaf(-LRc, bf2, sp.z);
            const float n3 = fmaf(-LRc, bf3, sp.w);
            sp.x = fmaxf(n0, 0.f); sp.y = fmaxf(n1, 0.f);
            sp.z = fmaxf(n2, 0.f); sp.w = fmaxf(n3, 0.f);
            spec[j] = sp;
            // rare clamp corrections: y_true += fb32 * (0 - cand)
            if (n0 < 0.f) {
                const float2 w32 = s_w01f[f + 0];
                atomicAdd(&s_corr[yb + ii.x], w32.x * (-n0));
                atomicAdd(&s_corr[yb + ii.x + 1], w32.y * (-n0));
            }
            if (n1 < 0.f) {
                const float2 w32 = s_w01f[f + 1];
                atomicAdd(&s_corr[yb + ii.y], w32.x * (-n1));
                atomicAdd(&s_corr[yb + ii.y + 1], w32.y * (-n1));
            }
            if (n2 < 0.f) {
                const float2 w32 = s_w01f[f + 2];
                atomicAdd(&s_corr[yb + ii.z], w32.x * (-n2));
                atomicAdd(&s_corr[yb + ii.z + 1], w32.y * (-n2));
            }
            if (n3 < 0.f) {
                const float2 w32 = s_w01f[f + 3];
                atomicAdd(&s_corr[yb + ii.w], w32.x * (-n3));
                atomicAdd(&s_corr[yb + ii.w + 1], w32.y * (-n3));
            }
        }
        __syncwarp();
    }

    // ---- epilogue: two chunks through stage, transposed coalesced stores ----
    // chunk 0: j in [0,9)  -> f in [0,576)
    __syncthreads();
    #pragma unroll
    for (int j = 0; j < 9; ++j)
        *reinterpret_cast<float4*>(s_stg + row * STSTR + 64 * j + 4 * q) = spec[j];
    __syncthreads();
    for (int f = tid; f < 576; f += NTHR) {
        const float* __restrict__ spp = s_stg + f;
        float* __restrict__ op = out + ((size_t)b * FF + f) * TT + t0;
        #pragma unroll
        for (int r = 0; r < ROWS; r += 4) {
            float4 v;
            v.x = spp[(r + 0) * STSTR];
            v.y = spp[(r + 1) * STSTR];
            v.z = spp[(r + 2) * STSTR];
            v.w = spp[(r + 3) * STSTR];
            *reinterpret_cast<float4*>(op + r) = v;
        }
    }
    // chunk 1: j in [9,17) -> f in [576,1088)
    __syncthreads();
    #pragma unroll
    for (int j = 9; j < NJ; ++j)
        *reinterpret_cast<float4*>(s_stg + row * STSTR + 64 * j + 4 * q - 576) = spec[j];
    __syncthreads();
    for (int fc = tid; fc < 512; fc += NTHR) {
        const int f = 576 + fc;
        if (f >= FF) continue;
        const float* __restrict__ spp = s_stg + fc;
        float* __restrict__ op = out + ((size_t)b * FF + f) * TT + t0;
        #pragma unroll
        for (int r = 0; r < ROWS; r += 4) {
            float4 v;
            v.x = spp[(r + 0) * STSTR];
            v.y = spp[(r + 1) * STSTR];
            v.z = spp[(r + 2) * STSTR];
            v.w = spp[(r + 3) * STSTR];
            *reinterpret_cast<float4*>(op + r) = v;
        }
    }
}

// ---------------- launch ----------------
extern "C" void kernel_launch(void* const* d_in, const int* in_sizes, int n_in,
                              void* d_out, int out_size) {
    const float* melspec   = (const float*)d_in[0];  // (4,128,1024)
    const float* spec_init = (const float*)d_in[1];  // (4,1024,1025)
    const float* fb        = (const float*)d_in[2];  // (1025,128)
    float* out             = (float*)d_out;          // (4,1025,1024)

    const int smem_bytes = SM_FLOATS * sizeof(float);   // 159040
    cudaFuncSetAttribute(invmel_kernel, cudaFuncAttributeMaxDynamicSharedMemorySize, smem_bytes);

    prep1_kernel<<<400, 128>>>(fb);
    prep2_kernel<<<MM, 128>>>(fb);
    invmel_kernel<<<NCTA, NTHR, smem_bytes>>>(melspec, spec_init, out);
}

// round 16
// speedup vs baseline: 1.5774x; 1.5774x over previous
#include <cuda_runtime.h>
#include <cuda_fp16.h>

// ---------------- problem constants ----------------
#define MM    128
#define FF    1025
#define FPc   1088
#define TT    1024
#define NITER 20
#define LRc   0.3f
#define MOMc  0.9f
#define INVc  (2.0f / 4096.0f)

#define ROWS  16             // rows per CTA; one warp per row
#define NTHR  512            // 16 warps
#define NCTA  256            // 256*16 = 4096; two waves
#define NJ    17             // 17 steps x 2 f = 34 f per lane
#define NC4M  12             // 4-half chunks per mel (48 slots >= max width ~46)
#define HSTR  1104           // fp16 shadow row stride (halves)
#define D2STR 264            // d2 row stride (floats; 132 float2 slots)
#define STSTR 1104           // epilogue stage row stride (floats), %32==16

// ---------------- persistent tables (same as R10) ----------------
__device__ __half2 g_w01h[FPc];        // (w0,w1) per bin, fp16
__device__ unsigned char g_i0[FPc];    // clamped first mel index (<=126)
__device__ uint2   g_csrh[NC4M*MM];    // chunk-major: 4 fp16 weights per chunk per mel
__device__ int     g_lonc[MM];         // lo | nc<<16

// ---------------- merged prep kernel ----------------
__global__ void prep_kernel(const float* __restrict__ fb) {
    const int blk = blockIdx.x;
    if (blk < 272) {
        const int warp = threadIdx.x >> 5;
        const int lane = threadIdx.x & 31;
        const int f = blk * 4 + warp;
        if (f >= FF) {
            if (f < FPc && lane == 0) { g_w01h[f] = __floats2half2_rn(0.f, 0.f); g_i0[f] = 0; }
            return;
        }
        const float* fr = fb + f * MM;
        unsigned b0 = __ballot_sync(0xffffffffu, fr[lane]      > 0.f);
        unsigned b1 = __ballot_sync(0xffffffffu, fr[lane + 32] > 0.f);
        unsigned b2 = __ballot_sync(0xffffffffu, fr[lane + 64] > 0.f);
        unsigned b3 = __ballot_sync(0xffffffffu, fr[lane + 96] > 0.f);
        if (lane == 0) {
            int fm = b0 ? (__ffs(b0) - 1)
                   : b1 ? (32 + __ffs(b1) - 1)
                   : b2 ? (64 + __ffs(b2) - 1)
                   : b3 ? (96 + __ffs(b3) - 1) : -1;
            if (fm < 0) {
                g_w01h[f] = __floats2half2_rn(0.f, 0.f); g_i0[f] = 0;
            } else {
                int i0 = fm > 126 ? 126 : fm;
                g_w01h[f] = __floats2half2_rn(fr[i0], fr[i0 + 1]);
                g_i0[f]   = (unsigned char)i0;
            }
        }
    } else {
        __shared__ int s_mn[128], s_mx[128];
        const int m = blk - 272;
        const int t = threadIdx.x;
        int mn = FF, mx = -1;
        for (int f = t; f < FF; f += 128) {
            if (fb[f * MM + m] > 0.f) { mn = min(mn, f); mx = max(mx, f); }
        }
        s_mn[t] = mn; s_mx[t] = mx;
        __syncthreads();
        for (int s = 64; s > 0; s >>= 1) {
            if (t < s) { s_mn[t] = min(s_mn[t], s_mn[t + s]); s_mx[t] = max(s_mx[t], s_mx[t + s]); }
            __syncthreads();
        }
        const int lo_al = (s_mx[0] < 0) ? 0 : (s_mn[0] & ~3);
        int cnt = (s_mx[0] < 0) ? 0 : (s_mx[0] + 1 - lo_al);
        int cnt_al = (cnt + 3) & ~3;
        if (cnt_al > 4 * NC4M) cnt_al = 4 * NC4M;
        if (t == 0) g_lonc[m] = lo_al | ((cnt_al >> 2) << 16);
        if (t < 4 * NC4M) {
            float w = (lo_al + t < FF) ? fb[(lo_al + t) * MM + m] : 0.f;
            reinterpret_cast<__half*>(g_csrh)[((t >> 2) * MM + m) * 4 + (t & 3)] = __float2half(w);
        }
    }
}

// ---------------- SMEM layout (float offsets) ----------------
#define OFF_SP16 0                                   // 16 * 1104 halves = 8832 floats
#define OFF_D2   (OFF_SP16 + ROWS * HSTR / 2)        // 8832 ; 16*264 = 4224
#define OFF_W01H (OFF_D2   + ROWS * D2STR)           // 13056 ; 1088
#define OFF_CSR  (OFF_W01H + FPc)                    // 14144 ; 3072 (uint2)
#define OFF_LONC (OFF_CSR  + 2 * NC4M * MM)          // 17216 ; 128
#define OFF_I0   (OFF_LONC + MM)                     // 17344 ; 272
#define OFF_STG  (OFF_I0   + FPc / 4)                // 17616 ; 16*1104 = 17664
#define SM_FLOATS (OFF_STG + ROWS * STSTR)           // 35280 floats = 141120 B

// ---------------- main kernel ----------------
__global__ __launch_bounds__(NTHR, 1)
void invmel_kernel(const float* __restrict__ melspec,
                   const float* __restrict__ spec_init,
                   float* __restrict__ out) {
    extern __shared__ float smem[];
    __half* s_sp16 = reinterpret_cast<__half*>(smem + OFF_SP16);
    float*  s_d2f  = smem + OFF_D2;
    float2* s_d2   = reinterpret_cast<float2*>(s_d2f);
    unsigned int* s_w01h = reinterpret_cast<unsigned int*>(smem + OFF_W01H);
    uint2*  s_csr2 = reinterpret_cast<uint2*>(smem + OFF_CSR);
    int*    s_lonc = reinterpret_cast<int*>(smem + OFF_LONC);
    unsigned char* s_i0 = reinterpret_cast<unsigned char*>(smem + OFF_I0);
    float*  s_stg  = smem + OFF_STG;

    const int tid  = threadIdx.x;
    const int row0 = blockIdx.x * ROWS;
    const int b    = row0 >> 10;
    const int t0   = row0 & 1023;

    // ---- tables ----
    for (int i = tid; i < FPc; i += NTHR) {
        s_w01h[i] = reinterpret_cast<const unsigned int*>(g_w01h)[i];
        s_i0[i]   = g_i0[i];
    }
    for (int i = tid; i < NC4M * MM; i += NTHR) s_csr2[i] = g_csrh[i];
    if (tid < MM) s_lonc[tid] = g_lonc[tid];

    // ---- roles: one warp per row ----
    const int row  = tid >> 5;        // 0..15
    const int lane = tid & 31;
    const int d2b  = row * (D2STR / 2);     // float2 index base
    __half* const sp16row = s_sp16 + row * HSTR;
    const size_t grow = (size_t)(row0 + row) * FF;

    // ---- spec master -> registers (34 f per lane: f = 64j + 2*lane) ----
    float2 spec[NJ];
    #pragma unroll
    for (int j = 0; j < NJ; ++j) {
        const int f = 64 * j + 2 * lane;
        float2 v;
        v.x = (f + 0 < FF) ? spec_init[grow + f + 0] : 0.f;
        v.y = (f + 1 < FF) ? spec_init[grow + f + 1] : 0.f;
        spec[j] = v;
        // fp16 shadow init
        *reinterpret_cast<__half2*>(sp16row + f) = __floats2half2_rn(v.x, v.y);
    }
    // ---- mel -> registers (4 per lane: m = 32j + lane) ----
    float mel4[4];
    #pragma unroll
    for (int j = 0; j < 4; ++j) {
        const int m = 32 * j + lane;
        mel4[j] = melspec[((size_t)b * MM + m) * TT + t0 + row];
    }

    int lonc4[4];
    float2 buf[NJ];
    #pragma unroll
    for (int j = 0; j < NJ; ++j) buf[j] = make_float2(0.f, 0.f);

    __syncthreads();   // tables visible (shadow rows are warp-private)

    #pragma unroll
    for (int j = 0; j < 4; ++j) lonc4[j] = s_lonc[32 * j + lane];

    for (int it = 0; it < NITER; ++it) {
        // ======== phase A: d[m] = mel[m] - sum_k w16(m,k)*spec16[lo+k] ========
        #pragma unroll
        for (int j = 0; j < 4; ++j) {
            const int m  = 32 * j + lane;
            const int lo = lonc4[j] & 0xffff;
            const int n  = lonc4[j] >> 16;
            const uint2* __restrict__ cw  = s_csr2 + m;
            const uint2* __restrict__ sp2 = reinterpret_cast<const uint2*>(sp16row + lo);
            float a0 = 0.f, a1 = 0.f;
            #pragma unroll 2
            for (int c = 0; c < n; ++c) {
                const uint2 wr = cw[c * MM];
                const uint2 sr = sp2[c];
                const float2 w0 = __half22float2(*reinterpret_cast<const __half2*>(&wr.x));
                const float2 w1 = __half22float2(*reinterpret_cast<const __half2*>(&wr.y));
                const float2 s0 = __half22float2(*reinterpret_cast<const __half2*>(&sr.x));
                const float2 s1 = __half22float2(*reinterpret_cast<const __half2*>(&sr.y));
                a0 = fmaf(w0.x, s0.x, a0);
                a1 = fmaf(w0.y, s0.y, a1);
                a0 = fmaf(w1.x, s1.x, a0);
                a1 = fmaf(w1.y, s1.y, a1);
            }
            const float d = mel4[j] - (a0 + a1);
            float dn = __shfl_down_sync(0xffffffffu, d, 1);
            if (j == 3 && lane == 31) dn = 0.f;            // d[128] pad
            // pair(m) = (d[m], d[m+1]); lane31's dn fixed by next group's lane0
            *reinterpret_cast<float2*>(s_d2f + row * D2STR + 2 * m) = make_float2(d, dn);
            if (j > 0 && lane == 0)
                s_d2f[row * D2STR + 2 * m - 1] = d;        // pair(32j-1).y = d[32j]
        }
        __syncwarp();

        // ======== phase C: regs spec/buf; dot = w0*d0 + w1*d1; fp16 shadow store ========
        #pragma unroll
        for (int j = 0; j < NJ; ++j) {
            const int f = 64 * j + 2 * lane;
            const uint2 wr = *reinterpret_cast<const uint2*>(s_w01h + f);   // 2 half2
            const uchar2 ii = *reinterpret_cast<const uchar2*>(s_i0 + f);
            const float2 wA = __half22float2(*reinterpret_cast<const __half2*>(&wr.x));
            const float2 wB = __half22float2(*reinterpret_cast<const __half2*>(&wr.y));
            const float2 dA = s_d2[d2b + ii.x];
            const float2 dB = s_d2[d2b + ii.y];
            const float dot0 = fmaf(wA.x, dA.x, wA.y * dA.y);
            const float dot1 = fmaf(wB.x, dB.x, wB.y * dB.y);
            float2 bv;
            bv.x = fmaf(MOMc, buf[j].x, -INVc * dot0);
            bv.y = fmaf(MOMc, buf[j].y, -INVc * dot1);
            buf[j] = bv;
            float2 sp = spec[j];
            sp.x = fmaxf(fmaf(-LRc, bv.x, sp.x), 0.f);
            sp.y = fmaxf(fmaf(-LRc, bv.y, sp.y), 0.f);
            spec[j] = sp;
            *reinterpret_cast<__half2*>(sp16row + f) = __floats2half2_rn(sp.x, sp.y);
        }
        __syncwarp();
    }

    // ---- regs -> stage ----
    #pragma unroll
    for (int j = 0; j < NJ; ++j)
        *reinterpret_cast<float2*>(s_stg + row * STSTR + 64 * j + 2 * lane) = spec[j];
    __syncthreads();

    // ---- epilogue: out[b][f][t0+r] = stage[r][f]; 4-row float4 groups ----
    for (int f = tid; f < FF; f += NTHR) {
        const float* __restrict__ spp = s_stg + f;
        float* __restrict__ op = out + ((size_t)b * FF + f) * TT + t0;
        #pragma unroll
        for (int r = 0; r < ROWS; r += 4) {
            float4 v;
            v.x = spp[(r + 0) * STSTR];
            v.y = spp[(r + 1) * STSTR];
            v.z = spp[(r + 2) * STSTR];
            v.w = spp[(r + 3) * STSTR];
            *reinterpret_cast<float4*>(op + r) = v;
        }
    }
}

// ---------------- launch ----------------
extern "C" void kernel_launch(void* const* d_in, const int* in_sizes, int n_in,
                              void* d_out, int out_size) {
    const float* melspec   = (const float*)d_in[0];  // (4,128,1024)
    const float* spec_init = (const float*)d_in[1];  // (4,1024,1025)
    const float* fb        = (const float*)d_in[2];  // (1025,128)
    float* out             = (float*)d_out;          // (4,1025,1024)

    const int smem_bytes = SM_FLOATS * sizeof(float);   // 141120
    cudaFuncSetAttribute(invmel_kernel, cudaFuncAttributeMaxDynamicSharedMemorySize, smem_bytes);

    prep_kernel<<<400, 128>>>(fb);
    invmel_kernel<<<NCTA, NTHR, smem_bytes>>>(melspec, spec_init, out);
}